// round 13
// baseline (speedup 1.0000x reference)
#include <cuda_runtime.h>
#include <math.h>

#define R    8      // amps per thread (reg bits = wires 5,6,7)
#define NBLK 16     // contexts: (b8, b9, b10, b11) = wires g8, g9, g17, g18

// cross-block combine scratch (no allocations allowed)
__device__ float    g_part[NBLK][8];
__device__ unsigned g_ctr = 0;

__device__ __forceinline__ float2 cmul(float2 a, float2 b) {
    return make_float2(a.x * b.x - a.y * b.y, a.x * b.y + a.y * b.x);
}
__device__ __forceinline__ float2 cadd(float2 a, float2 b) {
    return make_float2(a.x + b.x, a.y + b.y);
}
__device__ __forceinline__ float2 csub(float2 a, float2 b) {
    return make_float2(a.x - b.x, a.y - b.y);
}

// Fused single-qubit rotation (RZ?)*RY*RX for global wire gw, layer `layer`.
__device__ __forceinline__ void make_rot(int gw, int layer, bool withRZ,
                                         const float* __restrict__ inputs,
                                         const float* __restrict__ yw,
                                         const float* __restrict__ zw,
                                         float2 u[4])
{
    const float TWO_PI = 6.28318530717958647692f;
    const float PI_F   = 3.14159265358979323846f;
    float x = inputs[gw];
    float a;
    if (gw >= 17) {                            // directional wires 17,18
        a = (x >= 0.5f) ? PI_F : 0.0f;
    } else {                                   // [-1.5,1.5] -> [0,2pi], clip
        a = (x + 1.5f) * (TWO_PI / 3.0f);
        a = fminf(fmaxf(a, 0.0f), TWO_PI);
    }
    float sx, cx; sincosf(0.5f * a, &sx, &cx);
    float y = yw[layer * 19 + gw];
    float sy, cy; sincosf(0.5f * y, &sy, &cy);
    // M = RY*RX
    float2 m00 = make_float2(cy * cx,  sy * sx);
    float2 m01 = make_float2(-sy * cx, -cy * sx);
    float2 m10 = make_float2(sy * cx,  -cy * sx);
    float2 m11 = make_float2(cy * cx,  -sy * sx);
    if (withRZ) {
        float z = zw[layer * 19 + gw];
        float sz, cz; sincosf(0.5f * z, &sz, &cz);
        float2 e0 = make_float2(cz, -sz), e1 = make_float2(cz, sz);
        m00 = cmul(e0, m00); m01 = cmul(e0, m01);
        m10 = cmul(e1, m10); m11 = cmul(e1, m11);
    }
    u[0] = m00; u[1] = m01; u[2] = m10; u[3] = m11;
}

// Gate on register bit MB of the 8-amp register file.
template<int MB>
__device__ __forceinline__ void gate_reg(float* vr, float* vi, const float2* u)
{
    float2 u00 = u[0], u01 = u[1], u10 = u[2], u11 = u[3];
    #pragma unroll
    for (int r0 = 0; r0 < R; r0++) {
        if (r0 & MB) continue;
        int r1 = r0 | MB;
        float ar = vr[r0], ai = vi[r0], br = vr[r1], bi = vi[r1];
        vr[r0] = u00.x * ar - u00.y * ai + u01.x * br - u01.y * bi;
        vi[r0] = u00.x * ai + u00.y * ar + u01.x * bi + u01.y * br;
        vr[r1] = u10.x * ar - u10.y * ai + u11.x * br - u11.y * bi;
        vi[r1] = u10.x * ai + u10.y * ar + u11.x * bi + u11.y * br;
    }
}

// Gate on a lane bit (mask M) via warp shuffles.
template<int M>
__device__ __forceinline__ void gate_lane(float* vr, float* vi,
                                          unsigned lane, const float2* u)
{
    bool hi = (lane & M) != 0;
    float2 A = hi ? u[3] : u[0];
    float2 B = hi ? u[2] : u[1];
    #pragma unroll
    for (int r = 0; r < R; r++) {
        float wr = __shfl_xor_sync(0xFFFFFFFFu, vr[r], M);
        float wi = __shfl_xor_sync(0xFFFFFFFFu, vi[r], M);
        float ar = vr[r], ai = vi[r];
        vr[r] = A.x * ar - A.y * ai + B.x * wr - B.y * wi;
        vi[r] = A.x * ai + A.y * ar + B.x * wi + B.y * wr;
    }
}

// ============================================================================
// One warp per context (b8,b9,b10,b11) = basis bits of g8,g9,g17,g18.
// 256-amp register-resident statevector on wires 0..7:
//   amp bits a[4:0] = lane (wires 0-4), a[7:5] = reg (wires 5-7).
// Init = L0 product state x CZ0 sign x analytic L1 on g8,g18 (G tables).
// Then L1 w0-7, CZ1 sign, L2 w0-7, warp-reduced <Z_w>.
// Kept CZ0 pairs: (0,1)..(7,8),(8,9),(17,18),(0,18); CZ1: (0,1)..(7,8),(0,18).
// ============================================================================
__global__ void __launch_bounds__(32) qve_kernel(const float* __restrict__ inputs,
                                                 const float* __restrict__ yw,
                                                 const float* __restrict__ zw,
                                                 float* __restrict__ out)
{
    __shared__ float2 sPhi[8][2];   // L0 column-0 per wire 0..7
    __shared__ float2 sU1[8][4];    // L1 unitaries w0..7 (with RZ)
    __shared__ float2 sU2[8][4];    // L2 unitaries w0..7 (RY*RX)
    __shared__ float2 sG8[2][2];    // [x][b8]:  sum_i U1_8[b8,i] phi8[i] (-1)^(ix)
    __shared__ float2 sG18[2][2];   // [x][b11]: same for g18
    __shared__ float2 sP9[2];       // phi9  (g9  L0 col0, no RZ)
    __shared__ float2 sP10[2];      // phi17 (g17 L0 col0, no RZ)

    const unsigned lane = threadIdx.x;
    const unsigned ctx  = blockIdx.x;
    const unsigned b8  =  ctx       & 1u;
    const unsigned b9  = (ctx >> 1) & 1u;
    const unsigned b10 = (ctx >> 2) & 1u;
    const unsigned b11 = (ctx >> 3) & 1u;

    // ---- setup tables (disjoint lanes) ----
    if (lane < 8) {
        float2 u[4]; make_rot(lane, 1, true, inputs, yw, zw, u);
        sU1[lane][0] = u[0]; sU1[lane][1] = u[1];
        sU1[lane][2] = u[2]; sU1[lane][3] = u[3];
    } else if (lane < 16) {
        int w = lane - 8;
        float2 u[4]; make_rot(w, 2, false, inputs, yw, zw, u);
        sU2[w][0] = u[0]; sU2[w][1] = u[1]; sU2[w][2] = u[2]; sU2[w][3] = u[3];
    } else if (lane < 24) {
        int w = lane - 16;
        float2 u[4]; make_rot(w, 0, true, inputs, yw, zw, u);
        sPhi[w][0] = u[0]; sPhi[w][1] = u[2];
    } else if (lane == 24) {
        float2 u0[4]; make_rot(8, 0, true,  inputs, yw, zw, u0);   // phi8
        float2 u1[4]; make_rot(8, 1, false, inputs, yw, zw, u1);   // U1_8 (RZ drop)
        float2 p00 = cmul(u1[0], u0[0]), p01 = cmul(u1[1], u0[2]);
        sG8[0][0] = cadd(p00, p01); sG8[1][0] = csub(p00, p01);
        float2 p10 = cmul(u1[2], u0[0]), p11 = cmul(u1[3], u0[2]);
        sG8[0][1] = cadd(p10, p11); sG8[1][1] = csub(p10, p11);
    } else if (lane == 25) {
        float2 u[4]; make_rot(9, 0, false, inputs, yw, zw, u);     // phi9 (RZ drop)
        sP9[0] = u[0]; sP9[1] = u[2];
    } else if (lane == 26) {
        float2 u[4]; make_rot(17, 0, false, inputs, yw, zw, u);    // phi17 (RZ drop)
        sP10[0] = u[0]; sP10[1] = u[2];
    } else if (lane == 27) {
        float2 u0[4]; make_rot(18, 0, true,  inputs, yw, zw, u0);  // phi18 (RZ keep)
        float2 u1[4]; make_rot(18, 1, false, inputs, yw, zw, u1);  // U1_18 (RZ drop)
        float2 p00 = cmul(u1[0], u0[0]), p01 = cmul(u1[1], u0[2]);
        sG18[0][0] = cadd(p00, p01); sG18[1][0] = csub(p00, p01);
        float2 p10 = cmul(u1[2], u0[0]), p11 = cmul(u1[3], u0[2]);
        sG18[0][1] = cadd(p10, p11); sG18[1][1] = csub(p10, p11);
    }
    __syncwarp();

    // ---- init: product state x CZ0 sign x G8 x G18 ----
    // thread-constant factor (lane bits w0..4; context factors)
    float2 C = sPhi[0][lane & 1u];
    C = cmul(C, sPhi[1][(lane >> 1) & 1u]);
    C = cmul(C, sPhi[2][(lane >> 2) & 1u]);
    C = cmul(C, sPhi[3][(lane >> 3) & 1u]);
    C = cmul(C, sPhi[4][(lane >> 4) & 1u]);
    C = cmul(C, sP9[b9]);
    C = cmul(C, sP10[b10]);
    C = cmul(C, sG18[(lane & 1u) ^ b10][b11]);   // x = a0 ^ b10 (pairs (0,18),(17,18))

    float vr[R], vi[R];
    #pragma unroll
    for (int r = 0; r < R; r++) {
        float2 Pr = cmul(sPhi[5][r & 1], sPhi[6][(r >> 1) & 1]);
        Pr = cmul(Pr, sPhi[7][(r >> 2) & 1]);
        Pr = cmul(Pr, sG8[(((unsigned)r >> 2) & 1u) ^ b9][b8]); // x = a7 ^ b9
        float2 amp = cmul(C, Pr);
        unsigned a = ((unsigned)r << 5) | lane;
        // CZ0 core pairs (0,1)..(6,7)
        float s = (__popc((a & (a >> 1)) & 0x7Fu) & 1) ? -1.f : 1.f;
        vr[r] = s * amp.x; vi[r] = s * amp.y;
    }

    // ---- L1 rotations on wires 0..7 ----
    gate_lane<1 >(vr, vi, lane, sU1[0]);
    gate_lane<2 >(vr, vi, lane, sU1[1]);
    gate_lane<4 >(vr, vi, lane, sU1[2]);
    gate_lane<8 >(vr, vi, lane, sU1[3]);
    gate_lane<16>(vr, vi, lane, sU1[4]);
    gate_reg<1>(vr, vi, sU1[5]);
    gate_reg<2>(vr, vi, sU1[6]);
    gate_reg<4>(vr, vi, sU1[7]);

    // ---- CZ1 sign: core (0,1)..(6,7) + (7,8)->a7*b8 + (0,18)->a0*b11 ----
    #pragma unroll
    for (int r = 0; r < R; r++) {
        unsigned a = ((unsigned)r << 5) | lane;
        unsigned par = __popc((a & (a >> 1)) & 0x7Fu)
                     + ((((unsigned)r >> 2) & 1u) & b8)
                     + ((lane & 1u) & b11);
        if (par & 1u) { vr[r] = -vr[r]; vi[r] = -vi[r]; }
    }

    // ---- L2 rotations on wires 0..7 ----
    gate_lane<1 >(vr, vi, lane, sU2[0]);
    gate_lane<2 >(vr, vi, lane, sU2[1]);
    gate_lane<4 >(vr, vi, lane, sU2[2]);
    gate_lane<8 >(vr, vi, lane, sU2[3]);
    gate_lane<16>(vr, vi, lane, sU2[4]);
    gate_reg<1>(vr, vi, sU2[5]);
    gate_reg<2>(vr, vi, sU2[6]);
    gate_reg<4>(vr, vi, sU2[7]);

    // ---- partial <Z_w> for this context ----
    float P = 0.f, S5 = 0.f, S6 = 0.f, S7 = 0.f;
    #pragma unroll
    for (int r = 0; r < R; r++) {
        float p = vr[r] * vr[r] + vi[r] * vi[r];
        P  += p;
        S5 += (r & 1) ? -p : p;
        S6 += (r & 2) ? -p : p;
        S7 += (r & 4) ? -p : p;
    }
    float z[8];
    #pragma unroll
    for (int w = 0; w < 5; w++) z[w] = ((lane >> w) & 1u) ? -P : P;
    z[5] = S5; z[6] = S6; z[7] = S7;
    #pragma unroll
    for (int v = 0; v < 8; v++) {
        #pragma unroll
        for (int o = 16; o > 0; o >>= 1)
            z[v] += __shfl_xor_sync(0xFFFFFFFFu, z[v], o);
    }
    if (lane == 0) {
        #pragma unroll
        for (int v = 0; v < 8; v++) g_part[ctx][v] = z[v];
    }

    // ---- last block combines (fence + counter pattern) ----
    __threadfence();
    unsigned old = 0;
    if (lane == 0) old = atomicAdd(&g_ctr, 1u);
    old = __shfl_sync(0xFFFFFFFFu, old, 0);
    if (old == NBLK - 1) {
        __threadfence();
        if (lane < 8) {
            volatile float* gp = (volatile float*)g_part;
            float s = 0.f;
            #pragma unroll
            for (int b = 0; b < NBLK; b++) s += gp[b * 8 + lane];
            out[lane] = s;
        }
        if (lane == 0) g_ctr = 0;    // reset for next call (deterministic)
    }
}

extern "C" void kernel_launch(void* const* d_in, const int* in_sizes, int n_in,
                              void* d_out, int out_size)
{
    (void)in_sizes; (void)n_in; (void)out_size;
    const float* inputs = (const float*)d_in[0];
    const float* yw     = (const float*)d_in[1];
    const float* zw     = (const float*)d_in[2];
    float* out = (float*)d_out;

    qve_kernel<<<NBLK, 32>>>(inputs, yw, zw, out);
}

// round 14
// speedup vs baseline: 1.1905x; 1.1905x over previous
#include <cuda_runtime.h>
#include <math.h>

#define R    8      // amps per thread (reg bits = wires 5,6,7)
#define NCTX 16     // contexts: (b8, b9, b10, b11) = wires g8, g9, g17, g18
#define T    512    // 16 warps, one per context, single block

__device__ __forceinline__ float2 cmul(float2 a, float2 b) {
    return make_float2(a.x * b.x - a.y * b.y, a.x * b.y + a.y * b.x);
}
__device__ __forceinline__ float2 cadd(float2 a, float2 b) {
    return make_float2(a.x + b.x, a.y + b.y);
}
__device__ __forceinline__ float2 csub(float2 a, float2 b) {
    return make_float2(a.x - b.x, a.y - b.y);
}

// Fused single-qubit rotation (RZ?)*RY*RX for global wire gw, layer `layer`.
__device__ __forceinline__ void make_rot(int gw, int layer, bool withRZ,
                                         const float* __restrict__ inputs,
                                         const float* __restrict__ yw,
                                         const float* __restrict__ zw,
                                         float2 u[4])
{
    const float TWO_PI = 6.28318530717958647692f;
    const float PI_F   = 3.14159265358979323846f;
    float x = inputs[gw];
    float a;
    if (gw >= 17) {                            // directional wires 17,18
        a = (x >= 0.5f) ? PI_F : 0.0f;
    } else {                                   // [-1.5,1.5] -> [0,2pi], clip
        a = (x + 1.5f) * (TWO_PI / 3.0f);
        a = fminf(fmaxf(a, 0.0f), TWO_PI);
    }
    float sx, cx; __sincosf(0.5f * a, &sx, &cx);
    float y = yw[layer * 19 + gw];
    float sy, cy; __sincosf(0.5f * y, &sy, &cy);
    // M = RY*RX
    float2 m00 = make_float2(cy * cx,  sy * sx);
    float2 m01 = make_float2(-sy * cx, -cy * sx);
    float2 m10 = make_float2(sy * cx,  -cy * sx);
    float2 m11 = make_float2(cy * cx,  -sy * sx);
    if (withRZ) {
        float z = zw[layer * 19 + gw];
        float sz, cz; __sincosf(0.5f * z, &sz, &cz);
        float2 e0 = make_float2(cz, -sz), e1 = make_float2(cz, sz);
        m00 = cmul(e0, m00); m01 = cmul(e0, m01);
        m10 = cmul(e1, m10); m11 = cmul(e1, m11);
    }
    u[0] = m00; u[1] = m01; u[2] = m10; u[3] = m11;
}

// Gate on register bit MB of the 8-amp register file.
template<int MB>
__device__ __forceinline__ void gate_reg(float* vr, float* vi, const float2* u)
{
    float2 u00 = u[0], u01 = u[1], u10 = u[2], u11 = u[3];
    #pragma unroll
    for (int r0 = 0; r0 < R; r0++) {
        if (r0 & MB) continue;
        int r1 = r0 | MB;
        float ar = vr[r0], ai = vi[r0], br = vr[r1], bi = vi[r1];
        vr[r0] = u00.x * ar - u00.y * ai + u01.x * br - u01.y * bi;
        vi[r0] = u00.x * ai + u00.y * ar + u01.x * bi + u01.y * br;
        vr[r1] = u10.x * ar - u10.y * ai + u11.x * br - u11.y * bi;
        vi[r1] = u10.x * ai + u10.y * ar + u11.x * bi + u11.y * br;
    }
}

// Gate on a lane bit (mask M) via warp shuffles.
template<int M>
__device__ __forceinline__ void gate_lane(float* vr, float* vi,
                                          unsigned lane, const float2* u)
{
    bool hi = (lane & M) != 0;
    float2 A = hi ? u[3] : u[0];
    float2 B = hi ? u[2] : u[1];
    #pragma unroll
    for (int r = 0; r < R; r++) {
        float wr = __shfl_xor_sync(0xFFFFFFFFu, vr[r], M);
        float wi = __shfl_xor_sync(0xFFFFFFFFu, vi[r], M);
        float ar = vr[r], ai = vi[r];
        vr[r] = A.x * ar - A.y * ai + B.x * wr - B.y * wi;
        vi[r] = A.x * ai + A.y * ar + B.x * wi + B.y * wr;
    }
}

// ============================================================================
// One block, 16 warps; warp = context (b8,b9,b10,b11) = basis bits of
// g8,g9,g17,g18. Per warp: 256-amp register statevector on wires 0..7
// (a[4:0] = lane = wires 0-4, a[7:5] = reg = wires 5-7).
// Init = L0 product state x CZ0 sign x analytic L1 on g8,g18 (G tables).
// Then L1 w0-7, CZ1 sign, L2 w0-7, warp <Z_w> partials, smem combine.
// Kept CZ0 pairs: (0,1)..(7,8),(8,9),(17,18),(0,18); CZ1: (0,1)..(7,8),(0,18).
// ============================================================================
__global__ void __launch_bounds__(T) qve_kernel(const float* __restrict__ inputs,
                                                const float* __restrict__ yw,
                                                const float* __restrict__ zw,
                                                float* __restrict__ out)
{
    __shared__ float2 sPhi[8][2];   // L0 column-0 per wire 0..7
    __shared__ float2 sU1[8][4];    // L1 unitaries w0..7 (with RZ)
    __shared__ float2 sU2[8][4];    // L2 unitaries w0..7 (RY*RX)
    __shared__ float2 sG8[2][2];    // [x][b8]:  sum_i U1_8[b8,i] phi8[i] (-1)^(ix)
    __shared__ float2 sG18[2][2];   // [x][b11]: same for g18
    __shared__ float2 sP9[2];       // phi9  (g9  L0 col0, no RZ)
    __shared__ float2 sP17[2];      // phi17 (g17 L0 col0, no RZ)
    __shared__ float  sred[NCTX][8];

    const unsigned tid  = threadIdx.x;
    const unsigned lane = tid & 31u;
    const unsigned ctx  = tid >> 5;          // warp id = context
    const unsigned b8  =  ctx       & 1u;
    const unsigned b9  = (ctx >> 1) & 1u;
    const unsigned b10 = (ctx >> 2) & 1u;
    const unsigned b11 = (ctx >> 3) & 1u;

    // ---- setup tables: one job class per warp (parallel across warps) ----
    if (ctx == 0) {
        if (lane < 8) {
            float2 u[4]; make_rot(lane, 1, true, inputs, yw, zw, u);
            sU1[lane][0] = u[0]; sU1[lane][1] = u[1];
            sU1[lane][2] = u[2]; sU1[lane][3] = u[3];
        }
    } else if (ctx == 1) {
        if (lane < 8) {
            float2 u[4]; make_rot(lane, 2, false, inputs, yw, zw, u);
            sU2[lane][0] = u[0]; sU2[lane][1] = u[1];
            sU2[lane][2] = u[2]; sU2[lane][3] = u[3];
        }
    } else if (ctx == 2) {
        if (lane < 8) {
            float2 u[4]; make_rot(lane, 0, true, inputs, yw, zw, u);
            sPhi[lane][0] = u[0]; sPhi[lane][1] = u[2];
        }
    } else if (ctx == 3) {
        if (lane == 0) {
            float2 u0[4]; make_rot(8, 0, true,  inputs, yw, zw, u0);  // phi8
            float2 u1[4]; make_rot(8, 1, false, inputs, yw, zw, u1);  // U1_8 (RZ drop)
            float2 p00 = cmul(u1[0], u0[0]), p01 = cmul(u1[1], u0[2]);
            sG8[0][0] = cadd(p00, p01); sG8[1][0] = csub(p00, p01);
            float2 p10 = cmul(u1[2], u0[0]), p11 = cmul(u1[3], u0[2]);
            sG8[0][1] = cadd(p10, p11); sG8[1][1] = csub(p10, p11);
        } else if (lane == 1) {
            float2 u[4]; make_rot(9, 0, false, inputs, yw, zw, u);    // phi9
            sP9[0] = u[0]; sP9[1] = u[2];
        } else if (lane == 2) {
            float2 u[4]; make_rot(17, 0, false, inputs, yw, zw, u);   // phi17
            sP17[0] = u[0]; sP17[1] = u[2];
        } else if (lane == 3) {
            float2 u0[4]; make_rot(18, 0, true,  inputs, yw, zw, u0); // phi18
            float2 u1[4]; make_rot(18, 1, false, inputs, yw, zw, u1); // U1_18
            float2 p00 = cmul(u1[0], u0[0]), p01 = cmul(u1[1], u0[2]);
            sG18[0][0] = cadd(p00, p01); sG18[1][0] = csub(p00, p01);
            float2 p10 = cmul(u1[2], u0[0]), p11 = cmul(u1[3], u0[2]);
            sG18[0][1] = cadd(p10, p11); sG18[1][1] = csub(p10, p11);
        }
    }
    __syncthreads();

    // ---- init: product state x CZ0 sign x G8 x G18 ----
    float2 C = sPhi[0][lane & 1u];
    C = cmul(C, sPhi[1][(lane >> 1) & 1u]);
    C = cmul(C, sPhi[2][(lane >> 2) & 1u]);
    C = cmul(C, sPhi[3][(lane >> 3) & 1u]);
    C = cmul(C, sPhi[4][(lane >> 4) & 1u]);
    C = cmul(C, sP9[b9]);
    C = cmul(C, sP17[b10]);
    C = cmul(C, sG18[(lane & 1u) ^ b10][b11]);   // x = a0 ^ b10 (pairs (0,18),(17,18))

    float vr[R], vi[R];
    #pragma unroll
    for (int r = 0; r < R; r++) {
        float2 Pr = cmul(sPhi[5][r & 1], sPhi[6][(r >> 1) & 1]);
        Pr = cmul(Pr, sPhi[7][(r >> 2) & 1]);
        Pr = cmul(Pr, sG8[(((unsigned)r >> 2) & 1u) ^ b9][b8]);  // x = a7 ^ b9
        float2 amp = cmul(C, Pr);
        unsigned a = ((unsigned)r << 5) | lane;
        // CZ0 core pairs (0,1)..(6,7)
        float s = (__popc((a & (a >> 1)) & 0x7Fu) & 1) ? -1.f : 1.f;
        vr[r] = s * amp.x; vi[r] = s * amp.y;
    }

    // ---- L1 rotations on wires 0..7 ----
    gate_lane<1 >(vr, vi, lane, sU1[0]);
    gate_lane<2 >(vr, vi, lane, sU1[1]);
    gate_lane<4 >(vr, vi, lane, sU1[2]);
    gate_lane<8 >(vr, vi, lane, sU1[3]);
    gate_lane<16>(vr, vi, lane, sU1[4]);
    gate_reg<1>(vr, vi, sU1[5]);
    gate_reg<2>(vr, vi, sU1[6]);
    gate_reg<4>(vr, vi, sU1[7]);

    // ---- CZ1 sign: core (0,1)..(6,7) + (7,8)->a7*b8 + (0,18)->a0*b11 ----
    #pragma unroll
    for (int r = 0; r < R; r++) {
        unsigned a = ((unsigned)r << 5) | lane;
        unsigned par = __popc((a & (a >> 1)) & 0x7Fu)
                     + ((((unsigned)r >> 2) & 1u) & b8)
                     + ((lane & 1u) & b11);
        if (par & 1u) { vr[r] = -vr[r]; vi[r] = -vi[r]; }
    }

    // ---- L2 rotations on wires 0..7 ----
    gate_lane<1 >(vr, vi, lane, sU2[0]);
    gate_lane<2 >(vr, vi, lane, sU2[1]);
    gate_lane<4 >(vr, vi, lane, sU2[2]);
    gate_lane<8 >(vr, vi, lane, sU2[3]);
    gate_lane<16>(vr, vi, lane, sU2[4]);
    gate_reg<1>(vr, vi, sU2[5]);
    gate_reg<2>(vr, vi, sU2[6]);
    gate_reg<4>(vr, vi, sU2[7]);

    // ---- partial <Z_w> for this context ----
    float P = 0.f, S5 = 0.f, S6 = 0.f, S7 = 0.f;
    #pragma unroll
    for (int r = 0; r < R; r++) {
        float p = vr[r] * vr[r] + vi[r] * vi[r];
        P  += p;
        S5 += (r & 1) ? -p : p;
        S6 += (r & 2) ? -p : p;
        S7 += (r & 4) ? -p : p;
    }
    float z[8];
    #pragma unroll
    for (int w = 0; w < 5; w++) z[w] = ((lane >> w) & 1u) ? -P : P;
    z[5] = S5; z[6] = S6; z[7] = S7;
    #pragma unroll
    for (int v = 0; v < 8; v++) {
        #pragma unroll
        for (int o = 16; o > 0; o >>= 1)
            z[v] += __shfl_xor_sync(0xFFFFFFFFu, z[v], o);
    }
    if (lane == 0) {
        #pragma unroll
        for (int v = 0; v < 8; v++) sred[ctx][v] = z[v];
    }
    __syncthreads();

    // ---- combine 16 contexts, write out ----
    if (tid < 8) {
        float s = 0.f;
        #pragma unroll
        for (int b = 0; b < NCTX; b++) s += sred[b][tid];
        out[tid] = s;
    }
}

extern "C" void kernel_launch(void* const* d_in, const int* in_sizes, int n_in,
                              void* d_out, int out_size)
{
    (void)in_sizes; (void)n_in; (void)out_size;
    const float* inputs = (const float*)d_in[0];
    const float* yw     = (const float*)d_in[1];
    const float* zw     = (const float*)d_in[2];
    float* out = (float*)d_out;

    qve_kernel<<<1, T>>>(inputs, yw, zw, out);
}

// round 15
// speedup vs baseline: 1.8433x; 1.5484x over previous
#include <cuda_runtime.h>
#include <math.h>

// ============================================================================
// Per-observable light-cone simulation.
// <Z_w> depends on exactly 5 qubits (32 amps): one warp per observable,
// 1 amplitude per lane (lane bit i = local wire i).
// Kept gates per observable: 5 L0 rotations (analytic product-state init),
// 4 CZ0 pairs (fused sign), 3 L1 rotations (shuffle gates), 2 CZ1 pairs
// (fused sign), 1 L2 rotation (RY*RX; its RZ commutes with Z_w), then a
// warp-reduced expectation. No __syncthreads, no atomics, no global scratch.
// ============================================================================

// global wires of the 5-qubit cone, per observable w
__device__ const int d_phi[8][5] = {
    {0, 1, 2, 17, 18},   // w=0 (ring pair (0,18) pulls in 17,18)
    {0, 1, 2, 3, 18},    // w=1
    {0, 1, 2, 3, 4},     // w=2
    {1, 2, 3, 4, 5},     // w=3
    {2, 3, 4, 5, 6},     // w=4
    {3, 4, 5, 6, 7},     // w=5
    {4, 5, 6, 7, 8},     // w=6
    {5, 6, 7, 8, 9}      // w=7
};
// L1-rotated wires (global) and their local bit positions
__device__ const int d_l1w[8][3] = {
    {0, 1, 18}, {0, 1, 2}, {1, 2, 3}, {2, 3, 4},
    {3, 4, 5},  {4, 5, 6}, {5, 6, 7}, {6, 7, 8}
};
__device__ const int d_l1p[8][3] = {
    {0, 1, 4}, {0, 1, 2}, {1, 2, 3}, {1, 2, 3},
    {1, 2, 3}, {1, 2, 3}, {1, 2, 3}, {1, 2, 3}
};
// local bit of the measured wire
__device__ const int d_l2p[8] = {0, 1, 2, 2, 2, 2, 2, 2};
// kept CZ0 pairs (local bit indices)
__device__ const int d_cz0a[8][4] = {
    {0,1,0,3},{0,1,2,0},{0,1,2,3},{0,1,2,3},
    {0,1,2,3},{0,1,2,3},{0,1,2,3},{0,1,2,3}
};
__device__ const int d_cz0b[8][4] = {
    {1,2,4,4},{1,2,3,4},{1,2,3,4},{1,2,3,4},
    {1,2,3,4},{1,2,3,4},{1,2,3,4},{1,2,3,4}
};
// kept CZ1 pairs (local bit indices)
__device__ const int d_cz1a[8][2] = {
    {0,0},{0,1},{1,2},{1,2},{1,2},{1,2},{1,2},{1,2}
};
__device__ const int d_cz1b[8][2] = {
    {1,4},{1,2},{2,3},{2,3},{2,3},{2,3},{2,3},{2,3}
};

__device__ __forceinline__ float2 cmul(float2 a, float2 b) {
    return make_float2(a.x * b.x - a.y * b.y, a.x * b.y + a.y * b.x);
}

// Fused single-qubit rotation (RZ?)*RY*RX for global wire gw, layer `layer`.
__device__ __forceinline__ void make_rot(int gw, int layer, bool withRZ,
                                         const float* __restrict__ inputs,
                                         const float* __restrict__ yw,
                                         const float* __restrict__ zw,
                                         float2 u[4])
{
    const float TWO_PI = 6.28318530717958647692f;
    const float PI_F   = 3.14159265358979323846f;
    float x = inputs[gw];
    float a;
    if (gw >= 17) {                            // directional wires 17,18
        a = (x >= 0.5f) ? PI_F : 0.0f;
    } else {                                   // [-1.5,1.5] -> [0,2pi], clip
        a = (x + 1.5f) * (TWO_PI / 3.0f);
        a = fminf(fmaxf(a, 0.0f), TWO_PI);
    }
    float sx, cx; __sincosf(0.5f * a, &sx, &cx);
    float y = yw[layer * 19 + gw];
    float sy, cy; __sincosf(0.5f * y, &sy, &cy);
    // M = RY*RX
    float2 m00 = make_float2(cy * cx,  sy * sx);
    float2 m01 = make_float2(-sy * cx, -cy * sx);
    float2 m10 = make_float2(sy * cx,  -cy * sx);
    float2 m11 = make_float2(cy * cx,  -sy * sx);
    if (withRZ) {
        float z = zw[layer * 19 + gw];
        float sz, cz; __sincosf(0.5f * z, &sz, &cz);
        float2 e0 = make_float2(cz, -sz), e1 = make_float2(cz, sz);
        m00 = cmul(e0, m00); m01 = cmul(e0, m01);
        m10 = cmul(e1, m10); m11 = cmul(e1, m11);
    }
    u[0] = m00; u[1] = m01; u[2] = m10; u[3] = m11;
}

// Apply a 2x2 gate on local lane bit p to this lane's single amplitude.
__device__ __forceinline__ void apply_gate(float2& amp, unsigned lane, int p,
                                           const float2* u)
{
    unsigned M = 1u << p;
    float wr = __shfl_xor_sync(0xFFFFFFFFu, amp.x, M);
    float wi = __shfl_xor_sync(0xFFFFFFFFu, amp.y, M);
    bool hi = (lane >> p) & 1u;
    float2 A = hi ? u[3] : u[0];   // coefficient of own amp
    float2 B = hi ? u[2] : u[1];   // coefficient of partner amp
    float ar = amp.x, ai = amp.y;
    amp.x = A.x * ar - A.y * ai + B.x * wr - B.y * wi;
    amp.y = A.x * ai + A.y * ar + B.x * wi + B.y * wr;
}

__global__ void __launch_bounds__(256) qve_kernel(const float* __restrict__ inputs,
                                                  const float* __restrict__ yw,
                                                  const float* __restrict__ zw,
                                                  float* __restrict__ out)
{
    __shared__ float2 sU[8][9][4];   // per warp: 5 phi, 3 U1, 1 U2

    const unsigned tid  = threadIdx.x;
    const unsigned lane = tid & 31u;
    const unsigned w    = tid >> 5;          // warp id = observable index

    // ---- setup: lanes 0..8 each build one rotation for this warp ----
    if (lane < 5) {
        float2 u[4];
        make_rot(d_phi[w][lane], 0, true, inputs, yw, zw, u);
        sU[w][lane][0] = u[0]; sU[w][lane][1] = u[1];
        sU[w][lane][2] = u[2]; sU[w][lane][3] = u[3];
    } else if (lane < 8) {
        float2 u[4];
        make_rot(d_l1w[w][lane - 5], 1, true, inputs, yw, zw, u);
        sU[w][lane][0] = u[0]; sU[w][lane][1] = u[1];
        sU[w][lane][2] = u[2]; sU[w][lane][3] = u[3];
    } else if (lane == 8) {
        float2 u[4];
        make_rot((int)w, 2, false, inputs, yw, zw, u);   // L2: RY*RX only
        sU[w][8][0] = u[0]; sU[w][8][1] = u[1];
        sU[w][8][2] = u[2]; sU[w][8][3] = u[3];
    }
    __syncwarp();

    // ---- init: L0 product state (column 0 of each phi) ----
    float2 amp = sU[w][0][(lane & 1u) ? 2 : 0];
    #pragma unroll
    for (int j = 1; j < 5; j++)
        amp = cmul(amp, sU[w][j][((lane >> j) & 1u) ? 2 : 0]);

    // ---- CZ0 sign (4 kept pairs) ----
    {
        unsigned par = 0;
        #pragma unroll
        for (int k = 0; k < 4; k++)
            par += (lane >> d_cz0a[w][k]) & (lane >> d_cz0b[w][k]) & 1u;
        if (par & 1u) { amp.x = -amp.x; amp.y = -amp.y; }
    }

    // ---- L1 rotations (3 shuffle gates) ----
    apply_gate(amp, lane, d_l1p[w][0], sU[w][5]);
    apply_gate(amp, lane, d_l1p[w][1], sU[w][6]);
    apply_gate(amp, lane, d_l1p[w][2], sU[w][7]);

    // ---- CZ1 sign (2 kept pairs) ----
    {
        unsigned par = ((lane >> d_cz1a[w][0]) & (lane >> d_cz1b[w][0]) & 1u)
                     + ((lane >> d_cz1a[w][1]) & (lane >> d_cz1b[w][1]) & 1u);
        if (par & 1u) { amp.x = -amp.x; amp.y = -amp.y; }
    }

    // ---- L2 rotation on the measured wire ----
    const int pw = d_l2p[w];
    apply_gate(amp, lane, pw, sU[w][8]);

    // ---- <Z_w> = sum over lanes of (+-)|amp|^2 ----
    float p = amp.x * amp.x + amp.y * amp.y;
    float z = ((lane >> pw) & 1u) ? -p : p;
    #pragma unroll
    for (int o = 16; o > 0; o >>= 1)
        z += __shfl_xor_sync(0xFFFFFFFFu, z, o);

    if (lane == 0) out[w] = z;
}

extern "C" void kernel_launch(void* const* d_in, const int* in_sizes, int n_in,
                              void* d_out, int out_size)
{
    (void)in_sizes; (void)n_in; (void)out_size;
    const float* inputs = (const float*)d_in[0];
    const float* yw     = (const float*)d_in[1];
    const float* zw     = (const float*)d_in[2];
    float* out = (float*)d_out;

    qve_kernel<<<1, 256>>>(inputs, yw, zw, out);
}

// round 16
// speedup vs baseline: 1.9324x; 1.0483x over previous
#include <cuda_runtime.h>
#include <math.h>

// ============================================================================
// Per-observable light-cone simulation (see R15): <Z_w> depends on exactly
// 5 qubits -> 32 amps -> one warp per observable, 1 amplitude per lane.
// This revision removes ALL global-memory lookup tables (computed with
// uniform ALU instead) and makes the per-warp setup a single branchless
// path (RZ omission is encoded as z=0 -> identity fold).
// ============================================================================

__device__ __forceinline__ float2 cmul(float2 a, float2 b) {
    return make_float2(a.x * b.x - a.y * b.y, a.x * b.y + a.y * b.x);
}

// Apply a 2x2 gate on local lane bit p to this lane's single amplitude.
__device__ __forceinline__ void apply_gate(float2& amp, unsigned lane, int p,
                                           const float2* u)
{
    unsigned M = 1u << p;
    float wr = __shfl_xor_sync(0xFFFFFFFFu, amp.x, M);
    float wi = __shfl_xor_sync(0xFFFFFFFFu, amp.y, M);
    bool hi = (lane >> p) & 1u;
    float2 A = hi ? u[3] : u[0];   // coefficient of own amp
    float2 B = hi ? u[2] : u[1];   // coefficient of partner amp
    float ar = amp.x, ai = amp.y;
    amp.x = A.x * ar - A.y * ai + B.x * wr - B.y * wi;
    amp.y = A.x * ai + A.y * ar + B.x * wi + B.y * wr;
}

__global__ void __launch_bounds__(256) qve_kernel(const float* __restrict__ inputs,
                                                  const float* __restrict__ yw,
                                                  const float* __restrict__ zw,
                                                  float* __restrict__ out)
{
    __shared__ float2 sU[8][9][4];   // per warp: 5 phi (L0), 3 U1, 1 U2

    const unsigned tid  = threadIdx.x;
    const unsigned lane = tid & 31u;
    const int      w    = (int)(tid >> 5);    // warp id = observable index

    // ------------------------------------------------------------------
    // Setup: lanes 0..8 each build one fused rotation, single code path.
    //   j in [0,5):  layer 0 (with RZ),  gw = phi[w][j]
    //   j in [5,8):  layer 1 (with RZ),  gw = l1w[w][j-5]
    //   j == 8:      layer 2 (no RZ),    gw = w
    // Wire indices computed arithmetically (uniform ALU, no table loads).
    // ------------------------------------------------------------------
    if (lane < 9) {
        const int j = (int)lane;
        int gw, layer;
        bool withRZ;
        if (j < 5) {
            layer = 0; withRZ = true;
            gw = (w >= 2) ? (w - 2 + j)
               : (w == 0) ? ((j < 3) ? j : 14 + j)      // {0,1,2,17,18}
                          : ((j < 4) ? j : 18);          // {0,1,2,3,18}
        } else if (j < 8) {
            const int k = j - 5;
            layer = 1; withRZ = true;
            gw = (w >= 2) ? (w - 1 + k)
               : (w == 1) ? k
                          : ((k < 2) ? k : 18);          // {0,1,18}
        } else {
            layer = 2; withRZ = false; gw = w;
        }

        const float TWO_PI = 6.28318530717958647692f;
        const float PI_F   = 3.14159265358979323846f;
        float x = inputs[gw];
        float asc = (x + 1.5f) * (TWO_PI / 3.0f);
        asc = fminf(fmaxf(asc, 0.0f), TWO_PI);
        float adir = (x >= 0.5f) ? PI_F : 0.0f;
        float a = (gw >= 17) ? adir : asc;

        float sx, cx; __sincosf(0.5f * a, &sx, &cx);
        float y = yw[layer * 19 + gw];
        float sy, cy; __sincosf(0.5f * y, &sy, &cy);
        // M = RY*RX
        float2 m00 = make_float2( cy * cx,  sy * sx);
        float2 m01 = make_float2(-sy * cx, -cy * sx);
        float2 m10 = make_float2( sy * cx, -cy * sx);
        float2 m11 = make_float2( cy * cx, -sy * sx);
        // RZ fold; z = 0 when dropped (sincos(0) = (0,1) -> identity)
        float z = withRZ ? zw[layer * 19 + gw] : 0.0f;
        float sz, cz; __sincosf(0.5f * z, &sz, &cz);
        float2 e0 = make_float2(cz, -sz), e1 = make_float2(cz, sz);
        sU[w][j][0] = cmul(e0, m00); sU[w][j][1] = cmul(e0, m01);
        sU[w][j][2] = cmul(e1, m10); sU[w][j][3] = cmul(e1, m11);
    }
    __syncwarp();

    // ---- init: L0 product state (column 0 of each phi) ----
    float2 amp = sU[w][0][(lane & 1u) ? 2 : 0];
    #pragma unroll
    for (int j = 1; j < 5; j++)
        amp = cmul(amp, sU[w][j][((lane >> j) & 1u) ? 2 : 0]);

    // ---- CZ0 sign (4 kept pairs), uniform ALU ----
    {
        unsigned q = lane & (lane >> 1);     // bit k = bit_k & bit_{k+1}
        unsigned par;
        if (w >= 2)      par = __popc(q & 0xFu);                       // (0,1)(1,2)(2,3)(3,4)
        else if (w == 1) par = __popc(q & 0x7u)                        // (0,1)(1,2)(2,3)
                             + ((lane & (lane >> 4)) & 1u);            // (0,4)
        else             par = __popc(q & 0x3u)                        // (0,1)(1,2)
                             + ((lane & (lane >> 4)) & 1u)             // (0,4)
                             + (((lane >> 3) & (lane >> 4)) & 1u);     // (3,4)
        if (par & 1u) { amp.x = -amp.x; amp.y = -amp.y; }
    }

    // ---- L1 rotations (3 shuffle gates); positions via uniform selects ----
    {
        int p0, p1, p2;
        if (w >= 2)      { p0 = 1; p1 = 2; p2 = 3; }
        else if (w == 1) { p0 = 0; p1 = 1; p2 = 2; }
        else             { p0 = 0; p1 = 1; p2 = 4; }
        apply_gate(amp, lane, p0, sU[w][5]);
        apply_gate(amp, lane, p1, sU[w][6]);
        apply_gate(amp, lane, p2, sU[w][7]);
    }

    // ---- CZ1 sign (2 kept pairs) ----
    {
        unsigned q = lane & (lane >> 1);
        unsigned par;
        if (w >= 2)      par = __popc(q & 0x6u);                       // (1,2)(2,3)
        else if (w == 1) par = __popc(q & 0x3u);                       // (0,1)(1,2)
        else             par = (q & 1u)                                // (0,1)
                             + ((lane & (lane >> 4)) & 1u);            // (0,4)
        if (par & 1u) { amp.x = -amp.x; amp.y = -amp.y; }
    }

    // ---- L2 rotation on the measured wire ----
    const int pw = (w < 2) ? w : 2;
    apply_gate(amp, lane, pw, sU[w][8]);

    // ---- <Z_w> = sum over lanes of (+-)|amp|^2 ----
    float p = amp.x * amp.x + amp.y * amp.y;
    float zv = ((lane >> pw) & 1u) ? -p : p;
    #pragma unroll
    for (int o = 16; o > 0; o >>= 1)
        zv += __shfl_xor_sync(0xFFFFFFFFu, zv, o);

    if (lane == 0) out[w] = zv;
}

extern "C" void kernel_launch(void* const* d_in, const int* in_sizes, int n_in,
                              void* d_out, int out_size)
{
    (void)in_sizes; (void)n_in; (void)out_size;
    const float* inputs = (const float*)d_in[0];
    const float* yw     = (const float*)d_in[1];
    const float* zw     = (const float*)d_in[2];
    float* out = (float*)d_out;

    qve_kernel<<<1, 256>>>(inputs, yw, zw, out);
}